// round 14
// baseline (speedup 1.0000x reference)
#include <cuda_runtime.h>
#include <cuda_fp16.h>
#include <math.h>
#include <stdint.h>

#define BB    32
#define LL1   64
#define LL2   64
#define HH    256
#define FEATF 512

// f16 pre-converted operands
__device__ __half g_x1h[2048 * FEATF];
__device__ __half g_x2h[2048 * FEATF];
__device__ __half g_Wh[HH * 4 * HH];

// K-split partial outputs (a: k=[0,256), b: k=[256,512))
__device__ float g_y1a[BB * LL1 * HH];
__device__ float g_y1b[BB * LL1 * HH];
__device__ float g_y2a[BB * LL2 * HH];
__device__ float g_y2b[BB * LL2 * HH];

__device__ __forceinline__ uint32_t smem_u32(const void* p) {
    uint32_t a;
    asm("{ .reg .u64 t; cvta.to.shared.u64 t, %1; cvt.u32.u64 %0, t; }"
        : "=r"(a) : "l"(p));
    return a;
}
__device__ __forceinline__ void cp16(uint32_t dst, const void* src) {
    asm volatile("cp.async.cg.shared.global [%0], [%1], 16;" :: "r"(dst), "l"(src));
}
__device__ __forceinline__ void ldsm_x4(uint32_t* r, uint32_t addr) {
    asm volatile("ldmatrix.sync.aligned.m8n8.x4.shared.b16 {%0,%1,%2,%3}, [%4];"
                 : "=r"(r[0]), "=r"(r[1]), "=r"(r[2]), "=r"(r[3]) : "r"(addr));
}
__device__ __forceinline__ void mma_f16(float* c, const uint32_t* a,
                                        uint32_t b0, uint32_t b1) {
    asm volatile(
        "mma.sync.aligned.m16n8k16.row.col.f32.f16.f16.f32 "
        "{%0,%1,%2,%3}, {%4,%5,%6,%7}, {%8,%9}, {%0,%1,%2,%3};"
        : "+f"(c[0]), "+f"(c[1]), "+f"(c[2]), "+f"(c[3])
        : "r"(a[0]), "r"(a[1]), "r"(a[2]), "r"(a[3]), "r"(b0), "r"(b1));
}

// ---------------------------------------------------------------------------
// Pre-pass: f32 -> f16, MLP-optimized. Each thread batches 8 independent
// LDG.128 (128 B in flight), then converts and stores 8 x 8B.
// float4 counts: x1 262144 (128 blk), x2 262144 (128 blk), W 65536 (32 blk).
// Block 288 initializes out with the zero-padding bias term.
// ---------------------------------------------------------------------------
__global__ void __launch_bounds__(256)
preconv_kernel(const float* __restrict__ x1, const float* __restrict__ x2,
               const float* __restrict__ W,
               const int* __restrict__ sl1p, const int* __restrict__ sl2p,
               const float* __restrict__ bias, float* __restrict__ out)
{
    const int bid = blockIdx.x;
    if (bid < 288) {
        const float4* __restrict__ s;
        uint2* __restrict__ d;
        int base;
        if (bid < 128)      { s = (const float4*)x1; d = (uint2*)g_x1h; base = bid * 2048; }
        else if (bid < 256) { s = (const float4*)x2; d = (uint2*)g_x2h; base = (bid - 128) * 2048; }
        else                { s = (const float4*)W;  d = (uint2*)g_Wh;  base = (bid - 256) * 2048; }

        float4 v[8];
        #pragma unroll
        for (int q = 0; q < 8; q++)
            v[q] = s[base + q * 256 + threadIdx.x];

        #pragma unroll
        for (int q = 0; q < 8; q++) {
            __half2 lo = __floats2half2_rn(v[q].x, v[q].y);
            __half2 hi = __floats2half2_rn(v[q].z, v[q].w);
            uint2 w2;
            w2.x = *(uint32_t*)&lo;
            w2.y = *(uint32_t*)&hi;
            d[base + q * 256 + threadIdx.x] = w2;
        }
    } else {
        // out[b][h] = (4096 - n) * relu(bias[h]) / n
        for (int i = threadIdx.x; i < BB * HH; i += 256) {
            const int b = i >> 8, h = i & 255;
            const float n = (float)(sl1p[b] * sl2p[b]);
            out[i] = ((float)(LL1 * LL2) - n) * fmaxf(bias[h], 0.0f) / n;
        }
    }
}

// ---------------------------------------------------------------------------
// f16 GEMM via mma.m16n8k16 + ldmatrix.
// Y[4096, 256] = [x1;x2] @ [W1;W2]^T  (K-split 2 into a/b buffers).
// Grid (32 mT, 4 nT, 2 kS) = 256 CTAs, 256 threads = 8 warps (4m x 2n),
// CTA tile 128m x 64n, warp tile 32x32, K chunks of 64, cp.async dbl buffer.
// SMEM rows padded to 72 halves (144B).
// ---------------------------------------------------------------------------
#define HSTR   72
#define A_ST_H (128 * HSTR)            // 9216 halves / stage
#define B_ST_H (64 * HSTR)             // 4608 halves / stage
#define SMEM_GEMM ((2 * A_ST_H + 2 * B_ST_H) * 2)   // 55296 bytes

__global__ void __launch_bounds__(256)
gemm_f16()
{
    extern __shared__ __align__(16) __half sh[];
    const uint32_t smbase = smem_u32(sh);

    const int tid = threadIdx.x;
    const int wid = tid >> 5, lane = tid & 31;
    const int g = lane >> 2, t = lane & 3;

    const int mT = blockIdx.x;              // 0..31
    const int nT = blockIdx.y;              // 0..3
    const int kS = blockIdx.z;              // 0..1
    const int hf = (mT >= 16) ? 1 : 0;
    const __half* __restrict__ X = hf ? g_x2h : g_x1h;
    const int rowLoc = (mT & 15) * 128;
    const int hBase  = nT * 64;
    const int kOff   = kS * 256;
    const int wOff   = (hf ? FEATF : 0) + kOff;

    const int mw = wid & 3;                 // m warp: 0..3 (x32)
    const int nw = wid >> 2;                // n warp: 0..1 (x32)

    const int fr = tid >> 3;                // 0..31
    const int fsg = tid & 7;                // 8-half segment

    auto loadA = [&](int s, int c) {
        const uint32_t base = smbase + s * A_ST_H * 2;
        #pragma unroll
        for (int q = 0; q < 4; q++) {
            int row = fr + q * 32;          // 0..127
            cp16(base + (row * HSTR + fsg * 8) * 2,
                 X + (size_t)(rowLoc + row) * FEATF + kOff + c * 64 + fsg * 8);
        }
    };
    auto loadB = [&](int s, int c) {
        const uint32_t base = smbase + (2 * A_ST_H + s * B_ST_H) * 2;
        #pragma unroll
        for (int q = 0; q < 2; q++) {
            int row = fr + q * 32;          // 0..63
            cp16(base + (row * HSTR + fsg * 8) * 2,
                 g_Wh + (size_t)(hBase + row) * (4 * HH) + wOff + c * 64 + fsg * 8);
        }
    };

    const int aRow = lane & 15;
    const int aCol = (lane & 16) ? 8 : 0;
    const int bRow = (lane & 7) + ((lane & 16) ? 8 : 0);
    const int bCol = (lane & 8) ? 8 : 0;

    float acc[2][4][4];
    #pragma unroll
    for (int mf = 0; mf < 2; mf++)
        #pragma unroll
        for (int nf = 0; nf < 4; nf++)
            #pragma unroll
            for (int q = 0; q < 4; q++) acc[mf][nf][q] = 0.0f;

    loadA(0, 0); loadB(0, 0);
    asm volatile("cp.async.commit_group;" ::: "memory");

    const int NCH = 4;                      // 256 / 64
    for (int c = 0; c < NCH; c++) {
        if (c + 1 < NCH) {
            loadA((c + 1) & 1, c + 1);
            loadB((c + 1) & 1, c + 1);
            asm volatile("cp.async.commit_group;" ::: "memory");
            asm volatile("cp.async.wait_group 1;" ::: "memory");
        } else {
            asm volatile("cp.async.wait_group 0;" ::: "memory");
        }
        __syncthreads();

        const int s = c & 1;
        const uint32_t aStage = smbase + s * A_ST_H * 2;
        const uint32_t bStage = smbase + (2 * A_ST_H + s * B_ST_H) * 2;

        uint32_t a[2][4][4];
        #pragma unroll
        for (int mf = 0; mf < 2; mf++)
            #pragma unroll
            for (int kq = 0; kq < 4; kq++)
                ldsm_x4(a[mf][kq],
                        aStage + (((mw * 32 + mf * 16 + aRow) * HSTR) + kq * 16 + aCol) * 2);

        uint32_t b[2][4][4];
        #pragma unroll
        for (int q2 = 0; q2 < 2; q2++)
            #pragma unroll
            for (int kq = 0; kq < 4; kq++)
                ldsm_x4(b[q2][kq],
                        bStage + (((nw * 32 + q2 * 16 + bRow) * HSTR) + kq * 16 + bCol) * 2);

        #pragma unroll
        for (int kq = 0; kq < 4; kq++)
            #pragma unroll
            for (int mf = 0; mf < 2; mf++)
                #pragma unroll
                for (int nf = 0; nf < 4; nf++)
                    mma_f16(acc[mf][nf], a[mf][kq],
                            b[nf >> 1][kq][(nf & 1) * 2],
                            b[nf >> 1][kq][(nf & 1) * 2 + 1]);
        __syncthreads();
    }

    float* __restrict__ Y = hf ? (kS ? g_y2b : g_y2a)
                               : (kS ? g_y1b : g_y1a);
    #pragma unroll
    for (int mf = 0; mf < 2; mf++) {
        #pragma unroll
        for (int nf = 0; nf < 4; nf++) {
            const int row = rowLoc + mw * 32 + mf * 16 + g;
            const int h   = hBase + nw * 32 + nf * 8 + 2 * t;
            *(float2*)&Y[(size_t)row * HH + h]       = make_float2(acc[mf][nf][0], acc[mf][nf][1]);
            *(float2*)&Y[(size_t)(row + 8) * HH + h] = make_float2(acc[mf][nf][2], acc[mf][nf][3]);
        }
    }
}

// ---------------------------------------------------------------------------
// Pair reduction (partial over i-chunk of 16); sums K-split halves on load,
// bias folded into t2; scaled partial atomically added to out.
// Grid (8, 32, 4), 256 threads.
// ---------------------------------------------------------------------------
__global__ void __launch_bounds__(256)
pairsum_kernel(const int* __restrict__ sl1p, const int* __restrict__ sl2p,
               const float* __restrict__ bias, float* __restrict__ out)
{
    const int b  = blockIdx.y;
    const int hb = blockIdx.x;
    const int s  = blockIdx.z;
    const int tid = threadIdx.x;
    const int h  = tid & 31;
    const int jg = tid >> 5;

    const int sl1 = sl1p[b];
    const int sl2 = sl2p[b];
    const int i0  = s * 16;
    if (i0 >= sl1) return;

    __shared__ float y1s[16 * 32];
    {
        int i = tid >> 5, hh = tid & 31;
        int base0 = (b * LL1 + i0 + i)     * HH + hb * 32 + hh;
        int base1 = (b * LL1 + i0 + 8 + i) * HH + hb * 32 + hh;
        y1s[tid]       = g_y1a[base0] + g_y1b[base0];
        y1s[tid + 256] = g_y1a[base1] + g_y1b[base1];
    }
    __syncthreads();

    const float bh = bias[hb * 32 + h];
    float t2[8];
    #pragma unroll
    for (int k = 0; k < 8; k++) {
        int j = jg * 8 + k;
        int idx = (b * LL2 + j) * HH + hb * 32 + h;
        t2[k] = (j < sl2) ? (g_y2a[idx] + g_y2b[idx] + bh) : -INFINITY;
    }

    const int niter = min(16, sl1 - i0);
    float acc[8];
    #pragma unroll
    for (int k = 0; k < 8; k++) acc[k] = 0.0f;

    for (int i = 0; i < niter; i++) {
        float v = y1s[i * 32 + h];
        #pragma unroll
        for (int k = 0; k < 8; k++)
            acc[k] += fmaxf(v + t2[k], 0.0f);
    }

    float p = 0.0f;
    #pragma unroll
    for (int k = 0; k < 8; k++) p += acc[k];

    __shared__ float red[8][32];
    red[jg][h] = p;
    __syncthreads();
    if (jg == 0) {
        float ss = 0.0f;
        #pragma unroll
        for (int gg = 0; gg < 8; gg++) ss += red[gg][h];
        const float n = (float)(sl1 * sl2);
        atomicAdd(&out[b * HH + hb * 32 + h], ss / n);
    }
}

extern "C" void kernel_launch(void* const* d_in, const int* in_sizes, int n_in,
                              void* d_out, int out_size)
{
    const float* x1   = (const float*)d_in[0];
    const int*   sl1  = (const int*)  d_in[1];
    const float* x2   = (const float*)d_in[2];
    const int*   sl2  = (const int*)  d_in[3];
    const float* W    = (const float*)d_in[4];
    const float* bias = (const float*)d_in[5];
    float* out = (float*)d_out;

    cudaFuncSetAttribute(gemm_f16, cudaFuncAttributeMaxDynamicSharedMemorySize,
                         SMEM_GEMM);

    preconv_kernel<<<289, 256>>>(x1, x2, W, sl1, sl2, bias, out);
    gemm_f16<<<dim3(32, 4, 2), 256, SMEM_GEMM>>>();
    pairsum_kernel<<<dim3(8, 32, 4), 256>>>(sl1, sl2, bias, out);
}